// round 12
// baseline (speedup 1.0000x reference)
#include <cuda_runtime.h>

// Problem constants (from reference)
#define VOCAB   512
#define MAXLEN  512
#define BATCH   128
#define NFEAT   (VOCAB + VOCAB * VOCAB + 2)   // 262658

// FINAL (locked; best of series: cold 5.440us / timed 6.144us).
// One CTA per batch row, 512 threads, one position per thread.
// The dot product feat@W collapses to a gather-reduce over W: the [B, 262658]
// feature tensor is never materialized.
// Key mechanisms (each verified by measurement):
//  - W gathers issued UNCONDITIONALLY and length-masked after the loads
//    return: indices are always valid (unigram < 512, bigram <= 262655 <
//    NFEAT-2), and this removes the lengths-load -> predicate -> gather
//    serialization (an L2 round trip) from the critical path (R10: -0.22us).
//  - Neighbor action loaded directly as an independent 4B load with clamped
//    index (no shfl, no divergent branch on the gather path) (R5).
//  - Plain __syncthreads tail (7-cyc BAR floor beats named-barrier split, R11).
__global__ __launch_bounds__(512, 2)
void lr_ngram_kernel(const float* __restrict__ x,
                     const int*   __restrict__ lengths,
                     const float* __restrict__ W,
                     const float* __restrict__ bias,
                     float*       __restrict__ out)
{
    __shared__ float s_sum[16];
    __shared__ float s_max[16];

    const int b    = blockIdx.x;
    const int j    = threadIdx.x;          // position, 0..511
    const int lane = j & 31;
    const int wid  = j >> 5;

    const float* __restrict__ xr = x + (size_t)b * MAXLEN * 2;

    // Independent loads, all issued before anything depends on them:
    // x pair, neighbor action, and lengths (does not gate the gathers).
    const int jn = (j + 1 < MAXLEN) ? j + 1 : j;
    float2 at  = reinterpret_cast<const float2*>(xr)[j];     // (a_j, t_j)
    float  anf = __ldg(&xr[jn * 2]);                         // a_{j+1}
    const int len = __ldg(&lengths[b]);

    int a  = (int)at.x;
    int an = (int)anf;

    // Unconditional gathers (indices always in-range); mask afterwards.
    float wu = W[a];                                // unigram weight
    float wb = W[VOCAB + (a << 9) + an];            // bigram weight

    float sum = ((j     < len) ? wu : 0.0f)
              + ((j + 1 < len) ? wb : 0.0f);
    float tmax = (j < len) ? at.y : -3.402823466e38f;

    // Warp reduction (sum + max together).
    const unsigned m = 0xffffffffu;
    #pragma unroll
    for (int off = 16; off > 0; off >>= 1) {
        sum  += __shfl_down_sync(m, sum, off);
        tmax  = fmaxf(tmax, __shfl_down_sync(m, tmax, off));
    }
    if (lane == 0) { s_sum[wid] = sum; s_max[wid] = tmax; }
    __syncthreads();

    // Final reduction across 16 warps by warp 0.
    if (wid == 0) {
        sum  = (lane < 16) ? s_sum[lane] : 0.0f;
        tmax = (lane < 16) ? s_max[lane] : -3.402823466e38f;
        #pragma unroll
        for (int off = 8; off > 0; off >>= 1) {
            sum  += __shfl_down_sync(m, sum, off);
            tmax  = fmaxf(tmax, __shfl_down_sync(m, tmax, off));
        }
        if (lane == 0) {
            out[b] = sum
                   + tmax * W[NFEAT - 2]
                   + (float)len * W[NFEAT - 1]
                   + bias[0];
        }
    }
}

extern "C" void kernel_launch(void* const* d_in, const int* in_sizes, int n_in,
                              void* d_out, int out_size)
{
    const float* x       = (const float*)d_in[0];   // [B, MAXLEN, 2] f32
    const int*   lengths = (const int*)  d_in[1];   // [B] i32
    const float* W       = (const float*)d_in[2];   // [1, F] f32
    const float* bias    = (const float*)d_in[3];   // [1] f32
    float*       out     = (float*)d_out;           // [B, 1] f32

    lr_ngram_kernel<<<BATCH, 512>>>(x, lengths, W, bias, out);
}

// round 13
// speedup vs baseline: 1.1421x; 1.1421x over previous
#include <cuda_runtime.h>

// Problem constants (from reference)
#define VOCAB   512
#define MAXLEN  512
#define BATCH   128
#define NFEAT   (VOCAB + VOCAB * VOCAB + 2)   // 262658

// FINAL (locked; best variant of series: cold 5.44-5.60us, timed best 6.14us).
// One CTA per batch row, 512 threads, one position per thread.
// The dot product feat@W collapses to a gather-reduce over W: the [B, 262658]
// feature tensor is never materialized.
// Key mechanisms (measurement-verified across R1-R12):
//  - W gathers issued UNCONDITIONALLY and length-masked after the loads
//    return: indices are always valid (unigram < 512, bigram <= 262655 <
//    NFEAT-2), removing the lengths-load -> predicate -> gather
//    serialization (an L2/DRAM round trip) from the critical path (R10).
//  - Neighbor action loaded directly as an independent 4B load with clamped
//    index (no shfl, no divergent branch on the gather path) (R5).
//  - 16 warps/CTA saturates the latency-hiding benefit (R2/R4).
//  - Plain __syncthreads tail (beats named-barrier producer/consumer, R11).
__global__ __launch_bounds__(512, 2)
void lr_ngram_kernel(const float* __restrict__ x,
                     const int*   __restrict__ lengths,
                     const float* __restrict__ W,
                     const float* __restrict__ bias,
                     float*       __restrict__ out)
{
    __shared__ float s_sum[16];
    __shared__ float s_max[16];

    const int b    = blockIdx.x;
    const int j    = threadIdx.x;          // position, 0..511
    const int lane = j & 31;
    const int wid  = j >> 5;

    const float* __restrict__ xr = x + (size_t)b * MAXLEN * 2;

    // Independent loads, all issued before anything depends on them:
    // x pair, neighbor action, and lengths (does not gate the gathers).
    const int jn = (j + 1 < MAXLEN) ? j + 1 : j;
    float2 at  = reinterpret_cast<const float2*>(xr)[j];     // (a_j, t_j)
    float  anf = __ldg(&xr[jn * 2]);                         // a_{j+1}
    const int len = __ldg(&lengths[b]);

    int a  = (int)at.x;
    int an = (int)anf;

    // Unconditional gathers (indices always in-range); mask afterwards.
    float wu = W[a];                                // unigram weight
    float wb = W[VOCAB + (a << 9) + an];            // bigram weight

    float sum = ((j     < len) ? wu : 0.0f)
              + ((j + 1 < len) ? wb : 0.0f);
    float tmax = (j < len) ? at.y : -3.402823466e38f;

    // Warp reduction (sum + max together).
    const unsigned m = 0xffffffffu;
    #pragma unroll
    for (int off = 16; off > 0; off >>= 1) {
        sum  += __shfl_down_sync(m, sum, off);
        tmax  = fmaxf(tmax, __shfl_down_sync(m, tmax, off));
    }
    if (lane == 0) { s_sum[wid] = sum; s_max[wid] = tmax; }
    __syncthreads();

    // Final reduction across 16 warps by warp 0.
    if (wid == 0) {
        sum  = (lane < 16) ? s_sum[lane] : 0.0f;
        tmax = (lane < 16) ? s_max[lane] : -3.402823466e38f;
        #pragma unroll
        for (int off = 8; off > 0; off >>= 1) {
            sum  += __shfl_down_sync(m, sum, off);
            tmax  = fmaxf(tmax, __shfl_down_sync(m, tmax, off));
        }
        if (lane == 0) {
            out[b] = sum
                   + tmax * W[NFEAT - 2]
                   + (float)len * W[NFEAT - 1]
                   + bias[0];
        }
    }
}

extern "C" void kernel_launch(void* const* d_in, const int* in_sizes, int n_in,
                              void* d_out, int out_size)
{
    const float* x       = (const float*)d_in[0];   // [B, MAXLEN, 2] f32
    const int*   lengths = (const int*)  d_in[1];   // [B] i32
    const float* W       = (const float*)d_in[2];   // [1, F] f32
    const float* bias    = (const float*)d_in[3];   // [1] f32
    float*       out     = (float*)d_out;           // [B, 1] f32

    lr_ngram_kernel<<<BATCH, 512>>>(x, lengths, W, bias, out);
}